// round 2
// baseline (speedup 1.0000x reference)
#include <cuda_runtime.h>
#include <cuda_bf16.h>

// 2D Haar DWT, single level.
// Input  x  : (B=16, C=64, H=256, W=256) fp32
// Output out: (B, C*4, H/2=128, W/2=128) fp32, planes ordered [cA, cH, cV, cD]
//
// Each thread processes one (bc, h) row position and TWO output columns:
//   loads float4 from input rows 2h and 2h+1 (16B coalesced loads),
//   writes float2 to each of the 4 output planes (8B coalesced stores).

#define B_  16
#define C_  64
#define H_  256
#define W_  256
#define H2  (H_/2)          // 128
#define W2  (W_/2)          // 128
#define PAIRS (W2/2)        // 64 float2-outputs per output row
#define PLANE (H2*W2)       // 16384 elements per output plane

__global__ __launch_bounds__(256) void dwt_haar_kernel(
    const float* __restrict__ x, float* __restrict__ out)
{
    int idx = blockIdx.x * blockDim.x + threadIdx.x;
    // idx in [0, B*C*H2*PAIRS) = 16*64*128*64 = 8,388,608
    int wp = idx & (PAIRS - 1);            // which float4 along input row
    int h  = (idx >> 6) & (H2 - 1);        // output row
    int bc = idx >> 13;                    // 0 .. B*C-1 = 1023

    const float* row0 = x + (bc * H_ + 2 * h) * W_ + wp * 4;
    float4 t = *reinterpret_cast<const float4*>(row0);        // top row: a0 b0 a1 b1
    float4 u = *reinterpret_cast<const float4*>(row0 + W_);   // bot row: c0 d0 c1 d1

    float2 cA, cH, cV, cD;
    {
        float a = t.x, b = t.y, c = u.x, d = u.y;
        cA.x = (a + b + c + d) * 0.5f;
        cH.x = (c + d - a - b) * 0.5f;
        cV.x = (b + d - a - c) * 0.5f;
        cD.x = (a - b - c + d) * 0.5f;
    }
    {
        float a = t.z, b = t.w, c = u.z, d = u.w;
        cA.y = (a + b + c + d) * 0.5f;
        cH.y = (c + d - a - b) * 0.5f;
        cV.y = (b + d - a - c) * 0.5f;
        cD.y = (a - b - c + d) * 0.5f;
    }

    // output channel = bc*4 + k ; out[(bc*4 + k)*PLANE + h*W2 + 2*wp]
    float* obase = out + (bc * 4) * PLANE + h * W2 + 2 * wp;
    *reinterpret_cast<float2*>(obase)             = cA;
    *reinterpret_cast<float2*>(obase + PLANE)     = cH;
    *reinterpret_cast<float2*>(obase + 2 * PLANE) = cV;
    *reinterpret_cast<float2*>(obase + 3 * PLANE) = cD;
}

extern "C" void kernel_launch(void* const* d_in, const int* in_sizes, int n_in,
                              void* d_out, int out_size) {
    const float* x = (const float*)d_in[0];
    float* out = (float*)d_out;
    int total_threads = B_ * C_ * H2 * PAIRS;   // 8,388,608
    int block = 256;
    int grid = total_threads / block;           // 32768
    dwt_haar_kernel<<<grid, block>>>(x, out);
}

// round 3
// speedup vs baseline: 1.0016x; 1.0016x over previous
#include <cuda_runtime.h>
#include <cuda_bf16.h>

// 2D Haar DWT, single level.
// Input  x  : (B=16, C=64, H=256, W=256) fp32
// Output out: (B, C*4, H/2=128, W/2=128) fp32, planes ordered [cA, cH, cV, cD]
//
// Each thread processes one (bc, h) row position and FOUR output columns:
//   loads 2x float4 from input rows 2h and 2h+1 (streaming 16B loads),
//   writes one float4 to each of the 4 output planes (streaming 16B stores).

#define B_  16
#define C_  64
#define H_  256
#define W_  256
#define H2  (H_/2)          // 128
#define W2  (W_/2)          // 128
#define QUADS (W2/4)        // 32 float4-outputs per output row
#define PLANE (H2*W2)       // 16384 elements per output plane

__global__ __launch_bounds__(256) void dwt_haar_kernel(
    const float* __restrict__ x, float* __restrict__ out)
{
    int idx = blockIdx.x * blockDim.x + threadIdx.x;
    // idx in [0, B*C*H2*QUADS) = 16*64*128*32 = 4,194,304
    int wq = idx & (QUADS - 1);            // which group of 4 output cols
    int h  = (idx >> 5) & (H2 - 1);        // output row
    int bc = idx >> 12;                    // 0 .. B*C-1 = 1023

    const float4* row0 = reinterpret_cast<const float4*>(
        x + (bc * H_ + 2 * h) * W_ + wq * 8);
    const float4* row1 = reinterpret_cast<const float4*>(
        x + (bc * H_ + 2 * h + 1) * W_ + wq * 8);

    // 4 independent streaming loads up front (MLP=4)
    float4 t0 = __ldcs(row0);       // a0 b0 a1 b1
    float4 t1 = __ldcs(row0 + 1);   // a2 b2 a3 b3
    float4 u0 = __ldcs(row1);       // c0 d0 c1 d1
    float4 u1 = __ldcs(row1 + 1);   // c2 d2 c3 d3

    float4 cA, cH, cV, cD;
    {
        float a = t0.x, b = t0.y, c = u0.x, d = u0.y;
        cA.x = (a + b + c + d) * 0.5f;
        cH.x = (c + d - a - b) * 0.5f;
        cV.x = (b + d - a - c) * 0.5f;
        cD.x = (a - b - c + d) * 0.5f;
    }
    {
        float a = t0.z, b = t0.w, c = u0.z, d = u0.w;
        cA.y = (a + b + c + d) * 0.5f;
        cH.y = (c + d - a - b) * 0.5f;
        cV.y = (b + d - a - c) * 0.5f;
        cD.y = (a - b - c + d) * 0.5f;
    }
    {
        float a = t1.x, b = t1.y, c = u1.x, d = u1.y;
        cA.z = (a + b + c + d) * 0.5f;
        cH.z = (c + d - a - b) * 0.5f;
        cV.z = (b + d - a - c) * 0.5f;
        cD.z = (a - b - c + d) * 0.5f;
    }
    {
        float a = t1.z, b = t1.w, c = u1.z, d = u1.w;
        cA.w = (a + b + c + d) * 0.5f;
        cH.w = (c + d - a - b) * 0.5f;
        cV.w = (b + d - a - c) * 0.5f;
        cD.w = (a - b - c + d) * 0.5f;
    }

    // output channel = bc*4 + k ; out[(bc*4 + k)*PLANE + h*W2 + 4*wq]
    float4* obase = reinterpret_cast<float4*>(
        out + (bc * 4) * PLANE + h * W2 + 4 * wq);
    const int pstride = PLANE / 4;   // float4 stride between planes
    __stcs(obase,               cA);
    __stcs(obase + pstride,     cH);
    __stcs(obase + 2 * pstride, cV);
    __stcs(obase + 3 * pstride, cD);
}

extern "C" void kernel_launch(void* const* d_in, const int* in_sizes, int n_in,
                              void* d_out, int out_size) {
    const float* x = (const float*)d_in[0];
    float* out = (float*)d_out;
    int total_threads = B_ * C_ * H2 * QUADS;   // 4,194,304
    int block = 256;
    int grid = total_threads / block;           // 16384
    dwt_haar_kernel<<<grid, block>>>(x, out);
}